// round 1
// baseline (speedup 1.0000x reference)
#include <cuda_runtime.h>

#define B_ 4
#define T_ 2048
#define V_ 8192
#define D_ 256
#define M_ (B_*T_)   // 8192 rows of (b,t)

// Scratch (device globals — no allocation allowed in kernel_launch)
__device__ float g_q[M_*D_];
__device__ float g_k[M_*D_];
__device__ float g_v[M_*D_];
__device__ float g_r[M_*D_];

// ---------- packed f32x2 helpers (Blackwell FFMA2) ----------
__device__ __forceinline__ unsigned long long pk2(float a, float b){
    unsigned long long r; asm("mov.b64 %0, {%1, %2};" : "=l"(r) : "f"(a), "f"(b)); return r;
}
__device__ __forceinline__ unsigned long long bc2(float a){
    unsigned long long r; asm("mov.b64 %0, {%1, %1};" : "=l"(r) : "f"(a)); return r;
}
__device__ __forceinline__ unsigned long long ffma2(unsigned long long a,
                                                    unsigned long long b,
                                                    unsigned long long c){
    unsigned long long d; asm("fma.rn.f32x2 %0, %1, %2, %3;"
                              : "=l"(d) : "l"(a), "l"(b), "l"(c)); return d;
}
__device__ __forceinline__ void unpk(unsigned long long v, float& lo, float& hi){
    asm("mov.b64 {%0, %1}, %2;" : "=f"(lo), "=f"(hi) : "l"(v));
}

// ---------- generic NT SGEMM body: C[M,N] = A[M,K] * B[N,K]^T * scale ----------
// Block tile 128(M) x 64(N), BK=16, 256 threads, 8x4 micro-tile (f32x2 pairs along M).
template<int KDIM>
__device__ __forceinline__ void gemm_nt_128x64(
    const float* __restrict__ A, const float* __restrict__ Bm,
    float* __restrict__ C, int N, float scale)
{
    __shared__ __align__(16) float As[16][128];
    __shared__ __align__(16) float Bs[16][64];

    const int tid = threadIdx.x;
    const int tx  = tid & 15;   // col group (x4)
    const int ty  = tid >> 4;   // row group (x8)
    const int row0 = blockIdx.y * 128;
    const int col0 = blockIdx.x * 64;

    unsigned long long acc[4][4];
    #pragma unroll
    for (int i = 0; i < 4; ++i)
        #pragma unroll
        for (int j = 0; j < 4; ++j) acc[i][j] = 0ULL;

    const int brow = tid >> 2, bseg = tid & 3;

    for (int kk = 0; kk < KDIM; kk += 16) {
        // A tile: 128 rows x 16 k, transposed into As[k][m]
        #pragma unroll
        for (int q = 0; q < 2; ++q) {
            int idx = tid + q * 256;
            int r = idx >> 2, s = idx & 3;
            float4 a = *(const float4*)(A + (size_t)(row0 + r) * KDIM + kk + s * 4);
            As[s*4+0][r] = a.x; As[s*4+1][r] = a.y;
            As[s*4+2][r] = a.z; As[s*4+3][r] = a.w;
        }
        // B tile: 64 rows x 16 k, transposed into Bs[k][n]
        {
            float4 b = *(const float4*)(Bm + (size_t)(col0 + brow) * KDIM + kk + bseg * 4);
            Bs[bseg*4+0][brow] = b.x; Bs[bseg*4+1][brow] = b.y;
            Bs[bseg*4+2][brow] = b.z; Bs[bseg*4+3][brow] = b.w;
        }
        __syncthreads();

        #pragma unroll
        for (int k = 0; k < 16; ++k) {
            float4 a0 = *(const float4*)&As[k][ty*8];
            float4 a1 = *(const float4*)&As[k][ty*8+4];
            float4 bv = *(const float4*)&Bs[k][tx*4];
            unsigned long long am[4] = { pk2(a0.x,a0.y), pk2(a0.z,a0.w),
                                         pk2(a1.x,a1.y), pk2(a1.z,a1.w) };
            unsigned long long bb[4] = { bc2(bv.x), bc2(bv.y), bc2(bv.z), bc2(bv.w) };
            #pragma unroll
            for (int mi = 0; mi < 4; ++mi)
                #pragma unroll
                for (int nj = 0; nj < 4; ++nj)
                    acc[mi][nj] = ffma2(am[mi], bb[nj], acc[mi][nj]);
        }
        __syncthreads();
    }

    #pragma unroll
    for (int mi = 0; mi < 4; ++mi) {
        #pragma unroll
        for (int nj = 0; nj < 4; ++nj) {
            float lo, hi; unpk(acc[mi][nj], lo, hi);
            int r = row0 + ty*8 + mi*2;
            int c = col0 + tx*4 + nj;
            C[(size_t)r * N + c]       = lo * scale;
            C[(size_t)(r + 1) * N + c] = hi * scale;
        }
    }
}

// ---------- kernel 1: fused QKV projections ----------
__global__ void __launch_bounds__(256)
qkv_kernel(const float* __restrict__ x, const float* __restrict__ wq,
           const float* __restrict__ wk, const float* __restrict__ wv)
{
    const float* w = (blockIdx.z == 0) ? wq : (blockIdx.z == 1) ? wk : wv;
    float* out     = (blockIdx.z == 0) ? g_q : (blockIdx.z == 1) ? g_k : g_v;
    gemm_nt_128x64<V_>(x, w, out, D_, 1.0f);
}

// ---------- kernel 3: output projection ----------
__global__ void __launch_bounds__(256)
out_kernel(const float* __restrict__ wo, const float* __restrict__ out_scale,
           float* __restrict__ out)
{
    gemm_nt_128x64<D_>(g_r, wo, out, V_, out_scale[0]);
}

// ---------- kernel 2: decay-weighted attention ----------
// retrieved[b,i,:] = sum_{j>i} decay^(j-i-1) * (q_i . k_j) * v[b,j,:]
// Block: 64 query rows x 64 D-cols; loop key blocks jb >= ib with truncation.
__global__ void __launch_bounds__(256)
attn_kernel(const float* __restrict__ decay_logit_p)
{
    const int ib  = blockIdx.x;   // query block (of 64)
    const int dt  = blockIdx.y;   // D-tile (of 64)
    const int b   = blockIdx.z;
    const int tid = threadIdx.x;
    const int tx  = tid & 15;     // key-col / D-col group (x4)
    const int ty  = tid >> 4;     // query-row group (x4)

    // Shared: [qs|ks] (phase A) unioned with St (phase B A-operand), plus vs.
    __shared__ __align__(16) float smA[64][68];   // rows 0..31: qs[k][r], rows 32..63: ks[k][c]; later St[c][r]
    __shared__ __align__(16) float vs[64][68];

    float logit = decay_logit_p[0];
    float decay = 1.0f / (1.0f + expf(-logit));
    float l2d   = log2f(decay);   // < 0

    unsigned long long racc[2][4];
    #pragma unroll
    for (int i = 0; i < 2; ++i)
        #pragma unroll
        for (int j = 0; j < 4; ++j) racc[i][j] = 0ULL;

    const float* qbase = g_q + (size_t)(b*T_ + ib*64) * D_;

    for (int jb = ib; jb < T_/64; ++jb) {
        // truncation: max weight in this block pair is decay^emin (emin>0 off-diagonal)
        int emin = (jb - ib) * 64 - 64;
        if (emin > 0 && l2d * (float)emin < -50.0f) break;

        const float* kbase = g_k + (size_t)(b*T_ + jb*64) * D_;

        // ---- phase A: S = Q Kt (64x64), streamed over D in chunks of 32 ----
        unsigned long long sacc[2][4];
        #pragma unroll
        for (int i = 0; i < 2; ++i)
            #pragma unroll
            for (int j = 0; j < 4; ++j) sacc[i][j] = 0ULL;

        for (int dc = 0; dc < D_; dc += 32) {
            #pragma unroll
            for (int q2 = 0; q2 < 2; ++q2) {
                int idx = tid + q2 * 256;
                int r = idx >> 3, s = idx & 7;
                float4 a = *(const float4*)(qbase + (size_t)r * D_ + dc + s * 4);
                smA[s*4+0][r] = a.x; smA[s*4+1][r] = a.y;
                smA[s*4+2][r] = a.z; smA[s*4+3][r] = a.w;
                float4 bk = *(const float4*)(kbase + (size_t)r * D_ + dc + s * 4);
                smA[32 + s*4+0][r] = bk.x; smA[32 + s*4+1][r] = bk.y;
                smA[32 + s*4+2][r] = bk.z; smA[32 + s*4+3][r] = bk.w;
            }
            __syncthreads();
            #pragma unroll
            for (int k = 0; k < 32; ++k) {
                float4 a  = *(const float4*)&smA[k][ty*4];        // q rows
                float4 bv = *(const float4*)&smA[32 + k][tx*4];   // k cols
                unsigned long long am[2] = { pk2(a.x,a.y), pk2(a.z,a.w) };
                unsigned long long bb[4] = { bc2(bv.x), bc2(bv.y), bc2(bv.z), bc2(bv.w) };
                #pragma unroll
                for (int mi = 0; mi < 2; ++mi)
                    #pragma unroll
                    for (int nj = 0; nj < 4; ++nj)
                        sacc[mi][nj] = ffma2(am[mi], bb[nj], sacc[mi][nj]);
            }
            __syncthreads();
        }

        // ---- apply decay weights, write S transposed: St[c][r] (reuses smA) ----
        #pragma unroll
        for (int mi = 0; mi < 2; ++mi) {
            #pragma unroll
            for (int nj = 0; nj < 4; ++nj) {
                float lo, hi; unpk(sacc[mi][nj], lo, hi);
                int i0 = ib*64 + ty*4 + mi*2;      // global query row (lo)
                int j  = jb*64 + tx*4 + nj;        // global key col
                int n0 = j - i0;                   // diff for lo; hi has n0-1
                float w0 = (n0     > 0) ? exp2f(l2d * (float)(n0 - 1)) : 0.f;
                float w1 = (n0 - 1 > 0) ? exp2f(l2d * (float)(n0 - 2)) : 0.f;
                smA[tx*4+nj][ty*4 + mi*2]     = lo * w0;
                smA[tx*4+nj][ty*4 + mi*2 + 1] = hi * w1;
            }
        }

        // ---- load V tile (64 keys x 64 D-cols) ----
        const float* vbase = g_v + (size_t)(b*T_ + jb*64) * D_ + dt*64;
        #pragma unroll
        for (int q2 = 0; q2 < 4; ++q2) {
            int idx = tid + q2 * 256;
            int r = idx >> 4, s = idx & 15;
            float4 vv = *(const float4*)(vbase + (size_t)r * D_ + s * 4);
            *(float4*)&vs[r][s*4] = vv;
        }
        __syncthreads();

        // ---- phase B: out += St^T-indexed S @ V ----
        #pragma unroll
        for (int s = 0; s < 64; ++s) {
            float4 a  = *(const float4*)&smA[s][ty*4];   // St[s][query rows]
            float4 bv = *(const float4*)&vs[s][tx*4];
            unsigned long long am[2] = { pk2(a.x,a.y), pk2(a.z,a.w) };
            unsigned long long bb[4] = { bc2(bv.x), bc2(bv.y), bc2(bv.z), bc2(bv.w) };
            #pragma unroll
            for (int mi = 0; mi < 2; ++mi)
                #pragma unroll
                for (int nj = 0; nj < 4; ++nj)
                    racc[mi][nj] = ffma2(am[mi], bb[nj], racc[mi][nj]);
        }
        __syncthreads();
    }

    // ---- write retrieved tile ----
    float* rbase = g_r + (size_t)(b*T_ + ib*64) * D_ + dt*64;
    #pragma unroll
    for (int mi = 0; mi < 2; ++mi) {
        #pragma unroll
        for (int nj = 0; nj < 4; ++nj) {
            float lo, hi; unpk(racc[mi][nj], lo, hi);
            rbase[(size_t)(ty*4 + mi*2)     * D_ + tx*4 + nj] = lo;
            rbase[(size_t)(ty*4 + mi*2 + 1) * D_ + tx*4 + nj] = hi;
        }
    }
}

// ---------- launch ----------
extern "C" void kernel_launch(void* const* d_in, const int* in_sizes, int n_in,
                              void* d_out, int out_size)
{
    const float* x  = (const float*)d_in[0];
    const float* wq = (const float*)d_in[1];
    const float* wk = (const float*)d_in[2];
    const float* wv = (const float*)d_in[3];
    const float* wo = (const float*)d_in[4];
    const float* dl = (const float*)d_in[5];
    const float* os = (const float*)d_in[6];
    float* out = (float*)d_out;

    qkv_kernel<<<dim3(D_/64, M_/128, 3), 256>>>(x, wq, wk, wv);
    attn_kernel<<<dim3(T_/64, D_/64, B_), 256>>>(dl);
    out_kernel<<<dim3(V_/64, M_/128), 256>>>(wo, os, out);
}

// round 3
// speedup vs baseline: 2.0854x; 2.0854x over previous
#include <cuda_runtime.h>
#include <cuda_bf16.h>
#include <cstdint>

#define B_ 4
#define T_ 2048
#define V_ 8192
#define D_ 256
#define M_ (B_*T_)   // 8192 rows of (b,t)

// ---------------- scratch (device globals; no allocs allowed) ----------------
__device__ float g_q[M_*D_];
__device__ float g_k[M_*D_];
__device__ float g_v[M_*D_];
__device__ float g_r[M_*D_];

__device__ __nv_bfloat16 g_xh[(size_t)M_*V_];
__device__ __nv_bfloat16 g_xl[(size_t)M_*V_];
__device__ __nv_bfloat16 g_wh[3*(size_t)D_*V_];
__device__ __nv_bfloat16 g_wl[3*(size_t)D_*V_];
__device__ __nv_bfloat16 g_woh[(size_t)V_*D_];
__device__ __nv_bfloat16 g_wol[(size_t)V_*D_];
__device__ __nv_bfloat16 g_rh[(size_t)M_*D_];
__device__ __nv_bfloat16 g_rl[(size_t)M_*D_];

// ---------------- helpers ----------------
__device__ __forceinline__ uint32_t smem_u32(const void* p){
    uint32_t a;
    asm("{ .reg .u64 t; cvta.to.shared.u64 t, %1; cvt.u32.u64 %0, t; }" : "=r"(a) : "l"(p));
    return a;
}
#define CP16(smem, gptr) \
    asm volatile("cp.async.cg.shared.global [%0], [%1], 16;" :: "r"(smem), "l"(gptr))
#define CP_COMMIT() asm volatile("cp.async.commit_group;" ::: "memory")
#define CP_WAIT1()  asm volatile("cp.async.wait_group 1;" ::: "memory")
#define CP_WAIT0()  asm volatile("cp.async.wait_group 0;" ::: "memory")

__device__ __forceinline__ void ldsm_x4(uint32_t (&r)[4], uint32_t addr){
    asm volatile("ldmatrix.sync.aligned.m8n8.x4.shared.b16 {%0,%1,%2,%3}, [%4];"
        : "=r"(r[0]), "=r"(r[1]), "=r"(r[2]), "=r"(r[3]) : "r"(addr));
}
__device__ __forceinline__ void mma16816(float (&d)[4], const uint32_t (&a)[4],
                                         uint32_t b0, uint32_t b1){
    asm volatile("mma.sync.aligned.m16n8k16.row.col.f32.bf16.bf16.f32 "
        "{%0,%1,%2,%3}, {%4,%5,%6,%7}, {%8,%9}, {%0,%1,%2,%3};"
        : "+f"(d[0]), "+f"(d[1]), "+f"(d[2]), "+f"(d[3])
        : "r"(a[0]), "r"(a[1]), "r"(a[2]), "r"(a[3]), "r"(b0), "r"(b1));
}

// ---------------- packed f32x2 helpers (for attention) ----------------
__device__ __forceinline__ unsigned long long pk2(float a, float b){
    unsigned long long r; asm("mov.b64 %0, {%1, %2};" : "=l"(r) : "f"(a), "f"(b)); return r;
}
__device__ __forceinline__ unsigned long long bc2(float a){
    unsigned long long r; asm("mov.b64 %0, {%1, %1};" : "=l"(r) : "f"(a)); return r;
}
__device__ __forceinline__ unsigned long long ffma2(unsigned long long a,
                                                    unsigned long long b,
                                                    unsigned long long c){
    unsigned long long d; asm("fma.rn.f32x2 %0, %1, %2, %3;"
                              : "=l"(d) : "l"(a), "l"(b), "l"(c)); return d;
}
__device__ __forceinline__ void unpk(unsigned long long v, float& lo, float& hi){
    asm("mov.b64 {%0, %1}, %2;" : "=f"(lo), "=f"(hi) : "l"(v));
}

// ================= conversion kernel: fp32 -> bf16 hi/lo =================
__global__ void __launch_bounds__(256)
cvt_kernel(const float* __restrict__ in, int sel, int n)
{
    __nv_bfloat16 *hi, *lo;
    const float* src = in;
    switch (sel) {
        case 0: hi = g_xh;               lo = g_xl;               break;
        case 1: hi = g_wh;               lo = g_wl;               break;
        case 2: hi = g_wh + (size_t)D_*V_;   lo = g_wl + (size_t)D_*V_;   break;
        case 3: hi = g_wh + 2*(size_t)D_*V_; lo = g_wl + 2*(size_t)D_*V_; break;
        case 4: hi = g_woh;              lo = g_wol;              break;
        default: hi = g_rh;              lo = g_rl;  src = g_r;   break;
    }
    int i = (blockIdx.x * 256 + threadIdx.x) * 4;
    if (i >= n) return;
    float4 v = *(const float4*)(src + i);
    float f[4] = {v.x, v.y, v.z, v.w};
    union { __nv_bfloat16 b[4]; uint2 u; } H, L;
    #pragma unroll
    for (int j = 0; j < 4; ++j) {
        __nv_bfloat16 h = __float2bfloat16(f[j]);
        float r = f[j] - __bfloat162float(h);
        H.b[j] = h;
        L.b[j] = __float2bfloat16(r);
    }
    *(uint2*)(hi + i) = H.u;
    *(uint2*)(lo + i) = L.u;
}

// ================= HMMA split-precision NT GEMM =================
// C[M,N] = (Ah+Al)[M,K] * (Bh+Bl)[N,K]^T * scale  via Ah*Bh + Ah*Bl + Al*Bh
// CTA tile 128x128, BK=32, 256 threads, warp tile 64x32 (warp grid 2x4).
#define STG 40960            // bytes per stage
#define T_AH 0
#define T_AL 10240
#define T_BH 20480
#define T_BL 30720
#define LDS_B 80             // row stride in bytes (40 bf16)

__device__ __forceinline__ void hmma_gemm_body(
    const __nv_bfloat16* __restrict__ Agh, const __nv_bfloat16* __restrict__ Agl,
    const __nv_bfloat16* __restrict__ Bgh, const __nv_bfloat16* __restrict__ Bgl,
    float* __restrict__ C, int K, int ldC, float scale, int row0, int col0)
{
    extern __shared__ __align__(128) char sm[];
    const int tid  = threadIdx.x;
    const int lane = tid & 31;
    const int wid  = tid >> 5;
    const int wm   = wid >> 2;      // 0..1
    const int wn   = wid & 3;       // 0..3
    const uint32_t sbase = smem_u32(sm);

    float acc[4][4][4];
    #pragma unroll
    for (int a = 0; a < 4; ++a)
        #pragma unroll
        for (int b = 0; b < 4; ++b)
            #pragma unroll
            for (int c = 0; c < 4; ++c) acc[a][b][c] = 0.f;

    const int lrow = tid >> 2, lseg = tid & 3;

    auto load_stage = [&](int c, int s){
        const size_t k0 = (size_t)c * 32 + lseg * 8;
        const uint32_t sb = sbase + s * STG;
        #pragma unroll
        for (int h = 0; h < 2; ++h) {
            const int r = lrow + h * 64;
            const uint32_t soff = r * LDS_B + lseg * 16;
            CP16(sb + T_AH + soff, Agh + (size_t)(row0 + r) * K + k0);
            CP16(sb + T_AL + soff, Agl + (size_t)(row0 + r) * K + k0);
            CP16(sb + T_BH + soff, Bgh + (size_t)(col0 + r) * K + k0);
            CP16(sb + T_BL + soff, Bgl + (size_t)(col0 + r) * K + k0);
        }
    };

    // ldmatrix per-lane offsets
    const uint32_t offA = (lane & 15) * LDS_B + (lane >> 4) * 16;
    const uint32_t offB = ((lane & 7) + ((lane >> 4) & 1) * 8) * LDS_B
                        + ((lane >> 3) & 1) * 16;

    const int NC = K / 32;

    load_stage(0, 0);
    CP_COMMIT();

    for (int c = 0; c < NC; ++c) {
        if (c + 1 < NC) { load_stage(c + 1, (c + 1) & 1); CP_COMMIT(); CP_WAIT1(); }
        else            { CP_WAIT0(); }
        __syncthreads();

        const uint32_t sb = sbase + (c & 1) * STG;
        #pragma unroll
        for (int kk = 0; kk < 2; ++kk) {
            const uint32_t kb = kk * 32;   // bytes (16 bf16)
            uint32_t ah[4][4], al[4][4], bh[2][4], bl[2][4];
            #pragma unroll
            for (int mf = 0; mf < 4; ++mf)
                ldsm_x4(ah[mf], sb + T_AH + (wm*64 + mf*16) * LDS_B + kb + offA);
            #pragma unroll
            for (int g = 0; g < 2; ++g)
                ldsm_x4(bh[g], sb + T_BH + (wn*32 + g*16) * LDS_B + kb + offB);
            #pragma unroll
            for (int mf = 0; mf < 4; ++mf)
                #pragma unroll
                for (int nf = 0; nf < 4; ++nf)
                    mma16816(acc[mf][nf], ah[mf], bh[nf>>1][(nf&1)*2], bh[nf>>1][(nf&1)*2+1]);
            #pragma unroll
            for (int g = 0; g < 2; ++g)
                ldsm_x4(bl[g], sb + T_BL + (wn*32 + g*16) * LDS_B + kb + offB);
            #pragma unroll
            for (int mf = 0; mf < 4; ++mf)
                #pragma unroll
                for (int nf = 0; nf < 4; ++nf)
                    mma16816(acc[mf][nf], ah[mf], bl[nf>>1][(nf&1)*2], bl[nf>>1][(nf&1)*2+1]);
            #pragma unroll
            for (int mf = 0; mf < 4; ++mf)
                ldsm_x4(al[mf], sb + T_AL + (wm*64 + mf*16) * LDS_B + kb + offA);
            #pragma unroll
            for (int mf = 0; mf < 4; ++mf)
                #pragma unroll
                for (int nf = 0; nf < 4; ++nf)
                    mma16816(acc[mf][nf], al[mf], bh[nf>>1][(nf&1)*2], bh[nf>>1][(nf&1)*2+1]);
        }
        __syncthreads();
    }

    // epilogue: direct fp32 stores (float2 per frag-half)
    #pragma unroll
    for (int mf = 0; mf < 4; ++mf) {
        const int r0 = row0 + wm*64 + mf*16 + (lane >> 2);
        #pragma unroll
        for (int nf = 0; nf < 4; ++nf) {
            const int cc = col0 + wn*32 + nf*8 + (lane & 3) * 2;
            float2 v0 = { acc[mf][nf][0] * scale, acc[mf][nf][1] * scale };
            float2 v1 = { acc[mf][nf][2] * scale, acc[mf][nf][3] * scale };
            *(float2*)(C + (size_t)r0 * ldC + cc)       = v0;
            *(float2*)(C + (size_t)(r0 + 8) * ldC + cc) = v1;
        }
    }
}

// ---- QKV: grid (2 Ntiles, 64 Mtiles, 3 weights) ----
__global__ void __launch_bounds__(256, 1)
hmma_qkv_kernel()
{
    const int w = blockIdx.z;
    const __nv_bfloat16* Bh = g_wh + (size_t)w * D_ * V_;
    const __nv_bfloat16* Bl = g_wl + (size_t)w * D_ * V_;
    float* C = (w == 0) ? g_q : (w == 1) ? g_k : g_v;
    hmma_gemm_body(g_xh, g_xl, Bh, Bl, C, V_, D_, 1.0f,
                   blockIdx.y * 128, blockIdx.x * 128);
}

// ---- OUT: grid (64 Ntiles, 64 Mtiles) ----
__global__ void __launch_bounds__(256, 1)
hmma_out_kernel(const float* __restrict__ out_scale, float* __restrict__ out)
{
    hmma_gemm_body(g_rh, g_rl, g_woh, g_wol, out, D_, V_, out_scale[0],
                   blockIdx.y * 128, blockIdx.x * 128);
}

// ================= attention (fp32 FFMA2, unchanged) =================
__global__ void __launch_bounds__(256)
attn_kernel(const float* __restrict__ decay_logit_p)
{
    const int ib  = blockIdx.x;
    const int dt  = blockIdx.y;
    const int b   = blockIdx.z;
    const int tid = threadIdx.x;
    const int tx  = tid & 15;
    const int ty  = tid >> 4;

    __shared__ __align__(16) float smA[64][68];
    __shared__ __align__(16) float vs[64][68];

    float logit = decay_logit_p[0];
    float decay = 1.0f / (1.0f + expf(-logit));
    float l2d   = log2f(decay);

    unsigned long long racc[2][4];
    #pragma unroll
    for (int i = 0; i < 2; ++i)
        #pragma unroll
        for (int j = 0; j < 4; ++j) racc[i][j] = 0ULL;

    const float* qbase = g_q + (size_t)(b*T_ + ib*64) * D_;

    for (int jb = ib; jb < T_/64; ++jb) {
        int emin = (jb - ib) * 64 - 64;
        if (emin > 0 && l2d * (float)emin < -50.0f) break;

        const float* kbase = g_k + (size_t)(b*T_ + jb*64) * D_;

        unsigned long long sacc[2][4];
        #pragma unroll
        for (int i = 0; i < 2; ++i)
            #pragma unroll
            for (int j = 0; j < 4; ++j) sacc[i][j] = 0ULL;

        for (int dc = 0; dc < D_; dc += 32) {
            #pragma unroll
            for (int q2 = 0; q2 < 2; ++q2) {
                int idx = tid + q2 * 256;
                int r = idx >> 3, s = idx & 7;
                float4 a = *(const float4*)(qbase + (size_t)r * D_ + dc + s * 4);
                smA[s*4+0][r] = a.x; smA[s*4+1][r] = a.y;
                smA[s*4+2][r] = a.z; smA[s*4+3][r] = a.w;
                float4 bk = *(const float4*)(kbase + (size_t)r * D_ + dc + s * 4);
                smA[32 + s*4+0][r] = bk.x; smA[32 + s*4+1][r] = bk.y;
                smA[32 + s*4+2][r] = bk.z; smA[32 + s*4+3][r] = bk.w;
            }
            __syncthreads();
            #pragma unroll
            for (int k = 0; k < 32; ++k) {
                float4 a  = *(const float4*)&smA[k][ty*4];
                float4 bv = *(const float4*)&smA[32 + k][tx*4];
                unsigned long long am[2] = { pk2(a.x,a.y), pk2(a.z,a.w) };
                unsigned long long bb[4] = { bc2(bv.x), bc2(bv.y), bc2(bv.z), bc2(bv.w) };
                #pragma unroll
                for (int mi = 0; mi < 2; ++mi)
                    #pragma unroll
                    for (int nj = 0; nj < 4; ++nj)
                        sacc[mi][nj] = ffma2(am[mi], bb[nj], sacc[mi][nj]);
            }
            __syncthreads();
        }

        #pragma unroll
        for (int mi = 0; mi < 2; ++mi) {
            #pragma unroll
            for (int nj = 0; nj < 4; ++nj) {
                float lo, hi; unpk(sacc[mi][nj], lo, hi);
                int i0 = ib*64 + ty*4 + mi*2;
                int j  = jb*64 + tx*4 + nj;
                int n0 = j - i0;
                float w0 = (n0     > 0) ? exp2f(l2d * (float)(n0 - 1)) : 0.f;
                float w1 = (n0 - 1 > 0) ? exp2f(l2d * (float)(n0 - 2)) : 0.f;
                smA[tx*4+nj][ty*4 + mi*2]     = lo * w0;
                smA[tx*4+nj][ty*4 + mi*2 + 1] = hi * w1;
            }
        }

        const float* vbase = g_v + (size_t)(b*T_ + jb*64) * D_ + dt*64;
        #pragma unroll
        for (int q2 = 0; q2 < 4; ++q2) {
            int idx = tid + q2 * 256;
            int r = idx >> 4, s = idx & 15;
            float4 vv = *(const float4*)(vbase + (size_t)r * D_ + s * 4);
            *(float4*)&vs[r][s*4] = vv;
        }
        __syncthreads();

        #pragma unroll
        for (int s = 0; s < 64; ++s) {
            float4 a  = *(const float4*)&smA[s][ty*4];
            float4 bv = *(const float4*)&vs[s][tx*4];
            unsigned long long am[2] = { pk2(a.x,a.y), pk2(a.z,a.w) };
            unsigned long long bb[4] = { bc2(bv.x), bc2(bv.y), bc2(bv.z), bc2(bv.w) };
            #pragma unroll
            for (int mi = 0; mi < 2; ++mi)
                #pragma unroll
                for (int nj = 0; nj < 4; ++nj)
                    racc[mi][nj] = ffma2(am[mi], bb[nj], racc[mi][nj]);
        }
        __syncthreads();
    }

    float* rbase = g_r + (size_t)(b*T_ + ib*64) * D_ + dt*64;
    #pragma unroll
    for (int mi = 0; mi < 2; ++mi) {
        #pragma unroll
        for (int nj = 0; nj < 4; ++nj) {
            float lo, hi; unpk(racc[mi][nj], lo, hi);
            rbase[(size_t)(ty*4 + mi*2)     * D_ + tx*4 + nj] = lo;
            rbase[(size_t)(ty*4 + mi*2 + 1) * D_ + tx*4 + nj] = hi;
        }
    }
}

// ================= launch =================
#define DSMEM_BYTES (2*STG)

extern "C" void kernel_launch(void* const* d_in, const int* in_sizes, int n_in,
                              void* d_out, int out_size)
{
    const float* x  = (const float*)d_in[0];
    const float* wq = (const float*)d_in[1];
    const float* wk = (const float*)d_in[2];
    const float* wv = (const float*)d_in[3];
    const float* wo = (const float*)d_in[4];
    const float* dl = (const float*)d_in[5];
    const float* os = (const float*)d_in[6];
    float* out = (float*)d_out;

    static int configured = 0;
    if (!configured) {
        cudaFuncSetAttribute(hmma_qkv_kernel, cudaFuncAttributeMaxDynamicSharedMemorySize, DSMEM_BYTES);
        cudaFuncSetAttribute(hmma_out_kernel, cudaFuncAttributeMaxDynamicSharedMemorySize, DSMEM_BYTES);
        configured = 1;
    }

    cvt_kernel<<<(M_/4)*(V_/256), 256>>>(x,  0, M_*V_);
    cvt_kernel<<<(D_/4)*(V_/256), 256>>>(wq, 1, D_*V_);
    cvt_kernel<<<(D_/4)*(V_/256), 256>>>(wk, 2, D_*V_);
    cvt_kernel<<<(D_/4)*(V_/256), 256>>>(wv, 3, D_*V_);
    cvt_kernel<<<(D_/4)*(V_/256), 256>>>(wo, 4, D_*V_);

    hmma_qkv_kernel<<<dim3(2, 64, 3), 256, DSMEM_BYTES>>>();

    attn_kernel<<<dim3(T_/64, D_/64, B_), 256>>>(dl);

    cvt_kernel<<<(M_*D_)/1024, 256>>>(nullptr, 5, M_*D_);

    hmma_out_kernel<<<dim3(64, 64), 256, DSMEM_BYTES>>>(os, out);
}

// round 4
// speedup vs baseline: 2.7251x; 1.3067x over previous
#include <cuda_runtime.h>
#include <cuda_bf16.h>
#include <cstdint>

#define B_ 4
#define T_ 2048
#define V_ 8192
#define D_ 256
#define M_ (B_*T_)   // 8192 rows of (b,t)

// ---------------- scratch (device globals; no allocs allowed) ----------------
__device__ float g_q[M_*D_];
__device__ float g_k[M_*D_];
__device__ float g_v[M_*D_];
__device__ float g_r[M_*D_];

__device__ __nv_bfloat16 g_xh[(size_t)M_*V_];
__device__ __nv_bfloat16 g_xl[(size_t)M_*V_];
__device__ __nv_bfloat16 g_wh[3*(size_t)D_*V_];
__device__ __nv_bfloat16 g_wl[3*(size_t)D_*V_];
__device__ __nv_bfloat16 g_woh[(size_t)V_*D_];
__device__ __nv_bfloat16 g_wol[(size_t)V_*D_];
__device__ __nv_bfloat16 g_rh[(size_t)M_*D_];
__device__ __nv_bfloat16 g_rl[(size_t)M_*D_];

// bf16 hi/lo versions of q, k, v for HMMA attention
__device__ __nv_bfloat16 g_qbh[(size_t)M_*D_];
__device__ __nv_bfloat16 g_qbl[(size_t)M_*D_];
__device__ __nv_bfloat16 g_kbh[(size_t)M_*D_];
__device__ __nv_bfloat16 g_kbl[(size_t)M_*D_];
__device__ __nv_bfloat16 g_vbh[(size_t)M_*D_];
__device__ __nv_bfloat16 g_vbl[(size_t)M_*D_];

// ---------------- helpers ----------------
__device__ __forceinline__ uint32_t smem_u32(const void* p){
    uint32_t a;
    asm("{ .reg .u64 t; cvta.to.shared.u64 t, %1; cvt.u32.u64 %0, t; }" : "=r"(a) : "l"(p));
    return a;
}
#define CP16(smem, gptr) \
    asm volatile("cp.async.cg.shared.global [%0], [%1], 16;" :: "r"(smem), "l"(gptr))
#define CP_COMMIT() asm volatile("cp.async.commit_group;" ::: "memory")
#define CP_WAIT1()  asm volatile("cp.async.wait_group 1;" ::: "memory")
#define CP_WAIT0()  asm volatile("cp.async.wait_group 0;" ::: "memory")

__device__ __forceinline__ void ldsm_x4(uint32_t (&r)[4], uint32_t addr){
    asm volatile("ldmatrix.sync.aligned.m8n8.x4.shared.b16 {%0,%1,%2,%3}, [%4];"
        : "=r"(r[0]), "=r"(r[1]), "=r"(r[2]), "=r"(r[3]) : "r"(addr));
}
__device__ __forceinline__ void ldsm_x4_t(uint32_t (&r)[4], uint32_t addr){
    asm volatile("ldmatrix.sync.aligned.m8n8.x4.trans.shared.b16 {%0,%1,%2,%3}, [%4];"
        : "=r"(r[0]), "=r"(r[1]), "=r"(r[2]), "=r"(r[3]) : "r"(addr));
}
__device__ __forceinline__ void mma16816(float (&d)[4], const uint32_t (&a)[4],
                                         uint32_t b0, uint32_t b1){
    asm volatile("mma.sync.aligned.m16n8k16.row.col.f32.bf16.bf16.f32 "
        "{%0,%1,%2,%3}, {%4,%5,%6,%7}, {%8,%9}, {%0,%1,%2,%3};"
        : "+f"(d[0]), "+f"(d[1]), "+f"(d[2]), "+f"(d[3])
        : "r"(a[0]), "r"(a[1]), "r"(a[2]), "r"(a[3]), "r"(b0), "r"(b1));
}

// ================= conversion kernel: fp32 -> bf16 hi/lo =================
// 4 independent float4 loads per thread for MLP; n must be a multiple of 4096.
__global__ void __launch_bounds__(256)
cvt_kernel(const float* __restrict__ in, int sel, int n)
{
    __nv_bfloat16 *hi, *lo;
    const float* src = in;
    switch (sel) {
        case 0: hi = g_xh;               lo = g_xl;               break;
        case 1: hi = g_wh;               lo = g_wl;               break;
        case 2: hi = g_wh + (size_t)D_*V_;   lo = g_wl + (size_t)D_*V_;   break;
        case 3: hi = g_wh + 2*(size_t)D_*V_; lo = g_wl + 2*(size_t)D_*V_; break;
        case 4: hi = g_woh;              lo = g_wol;              break;
        case 5: hi = g_rh;               lo = g_rl;  src = g_r;   break;
        case 6: hi = g_qbh;              lo = g_qbl; src = g_q;   break;
        case 7: hi = g_kbh;              lo = g_kbl; src = g_k;   break;
        default: hi = g_vbh;             lo = g_vbl; src = g_v;   break;
    }
    const int base = blockIdx.x * 4096 + threadIdx.x * 4;
    float4 v[4];
    #pragma unroll
    for (int j = 0; j < 4; ++j) v[j] = *(const float4*)(src + base + j * 1024);
    #pragma unroll
    for (int j = 0; j < 4; ++j) {
        const int i = base + j * 1024;
        float f[4] = {v[j].x, v[j].y, v[j].z, v[j].w};
        union { __nv_bfloat16 b[4]; uint2 u; } H, L;
        #pragma unroll
        for (int e = 0; e < 4; ++e) {
            __nv_bfloat16 h = __float2bfloat16(f[e]);
            float r = f[e] - __bfloat162float(h);
            H.b[e] = h;
            L.b[e] = __float2bfloat16(r);
        }
        *(uint2*)(hi + i) = H.u;
        *(uint2*)(lo + i) = L.u;
    }
}

// ================= HMMA split-precision NT GEMM (unchanged from R3) =================
#define STG 40960
#define T_AH 0
#define T_AL 10240
#define T_BH 20480
#define T_BL 30720
#define LDS_B 80

__device__ __forceinline__ void hmma_gemm_body(
    const __nv_bfloat16* __restrict__ Agh, const __nv_bfloat16* __restrict__ Agl,
    const __nv_bfloat16* __restrict__ Bgh, const __nv_bfloat16* __restrict__ Bgl,
    float* __restrict__ C, int K, int ldC, float scale, int row0, int col0)
{
    extern __shared__ __align__(128) char sm[];
    const int tid  = threadIdx.x;
    const int lane = tid & 31;
    const int wid  = tid >> 5;
    const int wm   = wid >> 2;
    const int wn   = wid & 3;
    const uint32_t sbase = smem_u32(sm);

    float acc[4][4][4];
    #pragma unroll
    for (int a = 0; a < 4; ++a)
        #pragma unroll
        for (int b = 0; b < 4; ++b)
            #pragma unroll
            for (int c = 0; c < 4; ++c) acc[a][b][c] = 0.f;

    const int lrow = tid >> 2, lseg = tid & 3;

    auto load_stage = [&](int c, int s){
        const size_t k0 = (size_t)c * 32 + lseg * 8;
        const uint32_t sb = sbase + s * STG;
        #pragma unroll
        for (int h = 0; h < 2; ++h) {
            const int r = lrow + h * 64;
            const uint32_t soff = r * LDS_B + lseg * 16;
            CP16(sb + T_AH + soff, Agh + (size_t)(row0 + r) * K + k0);
            CP16(sb + T_AL + soff, Agl + (size_t)(row0 + r) * K + k0);
            CP16(sb + T_BH + soff, Bgh + (size_t)(col0 + r) * K + k0);
            CP16(sb + T_BL + soff, Bgl + (size_t)(col0 + r) * K + k0);
        }
    };

    const uint32_t offA = (lane & 15) * LDS_B + (lane >> 4) * 16;
    const uint32_t offB = ((lane & 7) + ((lane >> 4) & 1) * 8) * LDS_B
                        + ((lane >> 3) & 1) * 16;

    const int NC = K / 32;

    load_stage(0, 0);
    CP_COMMIT();

    for (int c = 0; c < NC; ++c) {
        if (c + 1 < NC) { load_stage(c + 1, (c + 1) & 1); CP_COMMIT(); CP_WAIT1(); }
        else            { CP_WAIT0(); }
        __syncthreads();

        const uint32_t sb = sbase + (c & 1) * STG;
        #pragma unroll
        for (int kk = 0; kk < 2; ++kk) {
            const uint32_t kb = kk * 32;
            uint32_t ah[4][4], al[4][4], bh[2][4], bl[2][4];
            #pragma unroll
            for (int mf = 0; mf < 4; ++mf)
                ldsm_x4(ah[mf], sb + T_AH + (wm*64 + mf*16) * LDS_B + kb + offA);
            #pragma unroll
            for (int g = 0; g < 2; ++g)
                ldsm_x4(bh[g], sb + T_BH + (wn*32 + g*16) * LDS_B + kb + offB);
            #pragma unroll
            for (int mf = 0; mf < 4; ++mf)
                #pragma unroll
                for (int nf = 0; nf < 4; ++nf)
                    mma16816(acc[mf][nf], ah[mf], bh[nf>>1][(nf&1)*2], bh[nf>>1][(nf&1)*2+1]);
            #pragma unroll
            for (int g = 0; g < 2; ++g)
                ldsm_x4(bl[g], sb + T_BL + (wn*32 + g*16) * LDS_B + kb + offB);
            #pragma unroll
            for (int mf = 0; mf < 4; ++mf)
                #pragma unroll
                for (int nf = 0; nf < 4; ++nf)
                    mma16816(acc[mf][nf], ah[mf], bl[nf>>1][(nf&1)*2], bl[nf>>1][(nf&1)*2+1]);
            #pragma unroll
            for (int mf = 0; mf < 4; ++mf)
                ldsm_x4(al[mf], sb + T_AL + (wm*64 + mf*16) * LDS_B + kb + offA);
            #pragma unroll
            for (int mf = 0; mf < 4; ++mf)
                #pragma unroll
                for (int nf = 0; nf < 4; ++nf)
                    mma16816(acc[mf][nf], al[mf], bh[nf>>1][(nf&1)*2], bh[nf>>1][(nf&1)*2+1]);
        }
        __syncthreads();
    }

    #pragma unroll
    for (int mf = 0; mf < 4; ++mf) {
        const int r0 = row0 + wm*64 + mf*16 + (lane >> 2);
        #pragma unroll
        for (int nf = 0; nf < 4; ++nf) {
            const int cc = col0 + wn*32 + nf*8 + (lane & 3) * 2;
            float2 v0 = { acc[mf][nf][0] * scale, acc[mf][nf][1] * scale };
            float2 v1 = { acc[mf][nf][2] * scale, acc[mf][nf][3] * scale };
            *(float2*)(C + (size_t)r0 * ldC + cc)       = v0;
            *(float2*)(C + (size_t)(r0 + 8) * ldC + cc) = v1;
        }
    }
}

__global__ void __launch_bounds__(256, 1)
hmma_qkv_kernel()
{
    const int w = blockIdx.z;
    const __nv_bfloat16* Bh = g_wh + (size_t)w * D_ * V_;
    const __nv_bfloat16* Bl = g_wl + (size_t)w * D_ * V_;
    float* C = (w == 0) ? g_q : (w == 1) ? g_k : g_v;
    hmma_gemm_body(g_xh, g_xl, Bh, Bl, C, V_, D_, 1.0f,
                   blockIdx.y * 128, blockIdx.x * 128);
}

__global__ void __launch_bounds__(256, 1)
hmma_out_kernel(const float* __restrict__ out_scale, float* __restrict__ out)
{
    hmma_gemm_body(g_rh, g_rl, g_woh, g_wol, out, D_, V_, out_scale[0],
                   blockIdx.y * 128, blockIdx.x * 128);
}

// ================= HMMA attention =================
// CTA: (query block of 64, batch). 8 warps: wm=wid>>1 (rows 16), wn=wid&1.
// Phase A: S[64,64] = 3-pass (Qh+Ql)(Kh+Kl)^T; weight; split hi/lo into smem.
// Phase B: out[64,256] += 3-pass (Sh+Sl)(Vh+Vl) with ldmatrix-trans V.
#define AT_STRIDE 528
#define SW_STRIDE 144
#define SM_QH 0
#define SM_QL 33792
#define SM_KH 67584
#define SM_KL 101376
#define SM_VH 135168
#define SM_VL 168960
#define SM_SWH 202752
#define SM_SWL 211968
#define ATT_SMEM 221184

__global__ void __launch_bounds__(256, 1)
attn_hmma_kernel(const float* __restrict__ dlp)
{
    extern __shared__ __align__(128) char shm[];
    const int tid = threadIdx.x, lane = tid & 31, wid = tid >> 5;
    const int wm = wid >> 1, wn = wid & 1;
    const int ib = blockIdx.x, b = blockIdx.y;
    const uint32_t sb = smem_u32(shm);

    const float logit = dlp[0];
    const float decay = 1.f / (1.f + expf(-logit));
    const float l2d   = log2f(decay);

    const int qrow0 = b * T_ + ib * 64;

    // ---- load Q hi/lo tiles ----
    #pragma unroll
    for (int it = 0; it < 8; ++it) {
        int idx = it * 256 + tid;
        int r = idx >> 5, s = idx & 31;
        uint32_t soff = r * AT_STRIDE + s * 16;
        size_t gb = ((size_t)(qrow0 + r) * D_) * 2 + s * 16;
        CP16(sb + SM_QH + soff, (const char*)g_qbh + gb);
        CP16(sb + SM_QL + soff, (const char*)g_qbl + gb);
    }
    CP_COMMIT();

    float oacc[8][2][4];
    #pragma unroll
    for (int a = 0; a < 8; ++a)
        #pragma unroll
        for (int g = 0; g < 2; ++g)
            #pragma unroll
            for (int e = 0; e < 4; ++e) oacc[a][g][e] = 0.f;

    const uint32_t offA  = (lane & 15) * AT_STRIDE + (lane >> 4) * 16;
    const uint32_t offB  = ((lane & 7) + ((lane >> 4) & 1) * 8) * AT_STRIDE
                         + ((lane >> 3) & 1) * 16;
    const uint32_t offAs = (lane & 15) * SW_STRIDE + (lane >> 4) * 16;
    const uint32_t offV  = ((lane & 7) + ((lane >> 3) & 1) * 8) * AT_STRIDE
                         + (lane >> 4) * 16;

    const int rl0 = wm * 16 + (lane >> 2);
    const float er0 = exp2f(-l2d * (float)rl0);
    const float er1 = er0 * exp2f(-l2d * 8.f);

    CP_WAIT0();
    __syncthreads();

    for (int jb = ib; jb < T_/64; ++jb) {
        int emin = (jb - ib) * 64 - 64;
        if (emin > 0 && l2d * (float)emin < -50.f) break;
        const int krow0 = b * T_ + jb * 64;

        // ---- issue K then V loads (two commit groups) ----
        #pragma unroll
        for (int it = 0; it < 8; ++it) {
            int idx = it * 256 + tid;
            int r = idx >> 5, s = idx & 31;
            uint32_t soff = r * AT_STRIDE + s * 16;
            size_t gb = ((size_t)(krow0 + r) * D_) * 2 + s * 16;
            CP16(sb + SM_KH + soff, (const char*)g_kbh + gb);
            CP16(sb + SM_KL + soff, (const char*)g_kbl + gb);
        }
        CP_COMMIT();
        #pragma unroll
        for (int it = 0; it < 8; ++it) {
            int idx = it * 256 + tid;
            int r = idx >> 5, s = idx & 31;
            uint32_t soff = r * AT_STRIDE + s * 16;
            size_t gb = ((size_t)(krow0 + r) * D_) * 2 + s * 16;
            CP16(sb + SM_VH + soff, (const char*)g_vbh + gb);
            CP16(sb + SM_VL + soff, (const char*)g_vbl + gb);
        }
        CP_COMMIT();
        CP_WAIT1();
        __syncthreads();

        // ---- phase A: S = Q K^T, 3-pass ----
        float sacc[4][4];
        #pragma unroll
        for (int nf = 0; nf < 4; ++nf)
            #pragma unroll
            for (int e = 0; e < 4; ++e) sacc[nf][e] = 0.f;

        #pragma unroll 4
        for (int kf = 0; kf < 16; ++kf) {
            const uint32_t kb = kf * 32;
            uint32_t qh[4], ql[4], kh[2][4], kl[2][4];
            ldsm_x4(qh, sb + SM_QH + (wm*16) * AT_STRIDE + kb + offA);
            ldsm_x4(ql, sb + SM_QL + (wm*16) * AT_STRIDE + kb + offA);
            ldsm_x4(kh[0], sb + SM_KH + (wn*32)      * AT_STRIDE + kb + offB);
            ldsm_x4(kh[1], sb + SM_KH + (wn*32 + 16) * AT_STRIDE + kb + offB);
            ldsm_x4(kl[0], sb + SM_KL + (wn*32)      * AT_STRIDE + kb + offB);
            ldsm_x4(kl[1], sb + SM_KL + (wn*32 + 16) * AT_STRIDE + kb + offB);
            #pragma unroll
            for (int nf = 0; nf < 4; ++nf) {
                mma16816(sacc[nf], qh, kh[nf>>1][(nf&1)*2], kh[nf>>1][(nf&1)*2+1]);
                mma16816(sacc[nf], qh, kl[nf>>1][(nf&1)*2], kl[nf>>1][(nf&1)*2+1]);
                mma16816(sacc[nf], ql, kh[nf>>1][(nf&1)*2], kh[nf>>1][(nf&1)*2+1]);
            }
        }

        // ---- weight + split hi/lo into Sw staging ----
        const float wbase = exp2f(l2d * (float)((jb - ib) * 64 - 1));
        const bool diag = (jb == ib);
        #pragma unroll
        for (int nf = 0; nf < 4; ++nf) {
            const int cl = wn*32 + nf*8 + (lane & 3)*2;
            float ec0 = exp2f(l2d * (float)cl);
            float ec1 = ec0 * decay;
            float w00 = wbase*ec0*er0, w01 = wbase*ec1*er0;
            float w10 = wbase*ec0*er1, w11 = wbase*ec1*er1;
            if (diag) {
                if (cl     <= rl0)     w00 = 0.f;
                if (cl + 1 <= rl0)     w01 = 0.f;
                if (cl     <= rl0 + 8) w10 = 0.f;
                if (cl + 1 <= rl0 + 8) w11 = 0.f;
            }
            float v00 = sacc[nf][0]*w00, v01 = sacc[nf][1]*w01;
            float v10 = sacc[nf][2]*w10, v11 = sacc[nf][3]*w11;

            #pragma unroll
            for (int h = 0; h < 2; ++h) {
                float a = h ? v10 : v00, c = h ? v11 : v01;
                __nv_bfloat16 ha = __float2bfloat16(a), hc = __float2bfloat16(c);
                float ra = a - __bfloat162float(ha), rc = c - __bfloat162float(hc);
                __nv_bfloat16 la = __float2bfloat16(ra), lc = __float2bfloat16(rc);
                uint32_t ph = (uint32_t)*(uint16_t*)&ha | ((uint32_t)*(uint16_t*)&hc << 16);
                uint32_t pl = (uint32_t)*(uint16_t*)&la | ((uint32_t)*(uint16_t*)&lc << 16);
                uint32_t off = (rl0 + h*8) * SW_STRIDE + cl * 2;
                *(uint32_t*)(shm + SM_SWH + off) = ph;
                *(uint32_t*)(shm + SM_SWL + off) = pl;
            }
        }

        CP_WAIT0();
        __syncthreads();   // Sw visible to all warps; V ready

        // ---- phase B: out += Sw @ V, 3-pass, V via ldmatrix-trans ----
        uint32_t sh4[4][4], sl4[4][4];
        #pragma unroll
        for (int kf = 0; kf < 4; ++kf) {
            ldsm_x4(sh4[kf], sb + SM_SWH + (wm*16) * SW_STRIDE + kf*32 + offAs);
            ldsm_x4(sl4[kf], sb + SM_SWL + (wm*16) * SW_STRIDE + kf*32 + offAs);
        }
        #pragma unroll
        for (int nb = 0; nb < 8; ++nb) {
            const uint32_t d0b = (uint32_t)(wn*128 + nb*16) * 2;
            #pragma unroll
            for (int kf = 0; kf < 4; ++kf) {
                uint32_t vh[4], vl[4];
                const uint32_t va = sb + (kf*16) * AT_STRIDE + d0b + offV;
                ldsm_x4_t(vh, va + SM_VH);
                ldsm_x4_t(vl, va + SM_VL);
                mma16816(oacc[nb][0], sh4[kf], vh[0], vh[1]);
                mma16816(oacc[nb][1], sh4[kf], vh[2], vh[3]);
                mma16816(oacc[nb][0], sh4[kf], vl[0], vl[1]);
                mma16816(oacc[nb][1], sh4[kf], vl[2], vl[3]);
                mma16816(oacc[nb][0], sl4[kf], vh[0], vh[1]);
                mma16816(oacc[nb][1], sl4[kf], vh[2], vh[3]);
            }
        }
        __syncthreads();   // K/V/Sw consumed; safe to overwrite next jb
    }

    // ---- epilogue ----
    float* rb = g_r + (size_t)(qrow0 + wm*16 + (lane >> 2)) * D_;
    #pragma unroll
    for (int nb = 0; nb < 8; ++nb) {
        #pragma unroll
        for (int g = 0; g < 2; ++g) {
            const int c = wn*128 + nb*16 + g*8 + (lane & 3) * 2;
            float2 v0 = { oacc[nb][g][0], oacc[nb][g][1] };
            float2 v1 = { oacc[nb][g][2], oacc[nb][g][3] };
            *(float2*)(rb + c)           = v0;
            *(float2*)(rb + 8 * D_ + c)  = v1;
        }
    }
}

// ================= launch =================
#define DSMEM_BYTES (2*STG)

extern "C" void kernel_launch(void* const* d_in, const int* in_sizes, int n_in,
                              void* d_out, int out_size)
{
    const float* x  = (const float*)d_in[0];
    const float* wq = (const float*)d_in[1];
    const float* wk = (const float*)d_in[2];
    const float* wv = (const float*)d_in[3];
    const float* wo = (const float*)d_in[4];
    const float* dl = (const float*)d_in[5];
    const float* os = (const float*)d_in[6];
    float* out = (float*)d_out;

    cudaFuncSetAttribute(hmma_qkv_kernel, cudaFuncAttributeMaxDynamicSharedMemorySize, DSMEM_BYTES);
    cudaFuncSetAttribute(hmma_out_kernel, cudaFuncAttributeMaxDynamicSharedMemorySize, DSMEM_BYTES);
    cudaFuncSetAttribute(attn_hmma_kernel, cudaFuncAttributeMaxDynamicSharedMemorySize, ATT_SMEM);

    cvt_kernel<<<((size_t)M_*V_)/4096, 256>>>(x,  0, M_*V_);
    cvt_kernel<<<((size_t)D_*V_)/4096, 256>>>(wq, 1, D_*V_);
    cvt_kernel<<<((size_t)D_*V_)/4096, 256>>>(wk, 2, D_*V_);
    cvt_kernel<<<((size_t)D_*V_)/4096, 256>>>(wv, 3, D_*V_);
    cvt_kernel<<<((size_t)D_*V_)/4096, 256>>>(wo, 4, D_*V_);

    hmma_qkv_kernel<<<dim3(2, 64, 3), 256, DSMEM_BYTES>>>();

    cvt_kernel<<<(M_*D_)/4096, 256>>>(nullptr, 6, M_*D_);
    cvt_kernel<<<(M_*D_)/4096, 256>>>(nullptr, 7, M_*D_);
    cvt_kernel<<<(M_*D_)/4096, 256>>>(nullptr, 8, M_*D_);

    attn_hmma_kernel<<<dim3(T_/64, B_), 256, ATT_SMEM>>>(dl);

    cvt_kernel<<<(M_*D_)/4096, 256>>>(nullptr, 5, M_*D_);

    hmma_out_kernel<<<dim3(64, 64), 256, DSMEM_BYTES>>>(os, out);
}